// round 2
// baseline (speedup 1.0000x reference)
#include <cuda_runtime.h>

// Problem constants (fixed by the reference)
#define NS   256
#define NT   16384
#define HH   64
#define EPS2 1e-16f

// 1-D table of the Pade network outputs as a function of feat = log(d/L)
#define TAB_N   16384
#define TAB_MIN -12.0f
#define TAB_MAX 4.0f
// entries at TAB_MIN + i*DT, i in [0, TAB_N-1]
#define TAB_DT     ((TAB_MAX - TAB_MIN) / (float)(TAB_N - 1))
#define TAB_INV_DT ((float)(TAB_N - 1) / (TAB_MAX - TAB_MIN))

static __device__ float2 g_tab[TAB_N];

// Exact evaluation of the H=64 Pade rational network at a given feat.
__device__ __forceinline__ void eval_exact(
    float feat,
    const float* __restrict__ W1, const float* __restrict__ b1,
    const float* __restrict__ pa, const float* __restrict__ pb,
    const float* __restrict__ W2, const float* __restrict__ b2,
    float& g0, float& g1)
{
    float acc0 = 0.0f, acc1 = 0.0f;
#pragma unroll 8
    for (int h = 0; h < HH; ++h) {
        float x   = fmaf(__ldg(&W1[h]), feat, __ldg(&b1[h]));
        float num = fmaf(fmaf(__ldg(&pa[3*h+2]), x, __ldg(&pa[3*h+1])), x, __ldg(&pa[3*h+0]));
        float den = 1.0f + fabsf(x * fmaf(__ldg(&pb[2*h+1]), x, __ldg(&pb[2*h+0])));
        float r   = num / den;
        acc0 = fmaf(__ldg(&W2[2*h+0]), r, acc0);
        acc1 = fmaf(__ldg(&W2[2*h+1]), r, acc1);
    }
    g0 = acc0 + __ldg(&b2[0]);
    g1 = acc1 + __ldg(&b2[1]);
}

__global__ void build_table_kernel(
    const float* __restrict__ W1, const float* __restrict__ b1,
    const float* __restrict__ pa, const float* __restrict__ pb,
    const float* __restrict__ W2, const float* __restrict__ b2)
{
    int i = blockIdx.x * blockDim.x + threadIdx.x;
    if (i >= TAB_N) return;
    float feat = TAB_MIN + (float)i * TAB_DT;
    float g0, g1;
    eval_exact(feat, W1, b1, pa, pb, W2, b2, g0, g1);
    g_tab[i] = make_float2(g0, g1);
}

// 32 targets per block of 256 threads.
// warp = 32 targets (one per lane) x one 32-source chunk (row = tid>>5).
__global__ void __launch_bounds__(256) field_kernel(
    const float* __restrict__ ref_len,
    const float* __restrict__ sp,   // [NS,3]
    const float* __restrict__ tp,   // [NT,3]
    const float* __restrict__ q,    // [NS]
    const float* __restrict__ W1, const float* __restrict__ b1,
    const float* __restrict__ pa, const float* __restrict__ pb,
    const float* __restrict__ W2, const float* __restrict__ b2,
    float* __restrict__ out)        // [NT,4]
{
    __shared__ float4 s_src[NS];          // xyz + strength
    __shared__ float4 s_red[8][33];       // padded to dodge bank conflicts

    int tid = threadIdx.x;
    for (int s = tid; s < NS; s += 256) {
        s_src[s] = make_float4(sp[3*s+0], sp[3*s+1], sp[3*s+2], q[s]);
    }

    int lane = tid & 31;
    int row  = tid >> 5;
    int tg   = blockIdx.x * 32 + lane;

    float tx = tp[3*tg+0];
    float ty = tp[3*tg+1];
    float tz = tp[3*tg+2];
    float logL = __logf(ref_len[0]);

    __syncthreads();

    float a0 = 0.0f, a1 = 0.0f, a2 = 0.0f, a3 = 0.0f;

    int s0 = row * 32;
#pragma unroll 4
    for (int si = 0; si < 32; ++si) {
        float4 sv = s_src[s0 + si];       // same address across warp -> broadcast
        float dx = tx - sv.x;
        float dy = ty - sv.y;
        float dz = tz - sv.z;
        float d2 = fmaf(dx, dx, fmaf(dy, dy, fmaf(dz, dz, EPS2)));
        float inv_d = rsqrtf(d2);
        float feat  = fmaf(0.5f, __logf(d2), -logL);   // log(sqrt(d2)) - log(L)

        float t = (feat - TAB_MIN) * TAB_INV_DT;
        float g0, g1;
        if (t >= 0.0f && t < (float)(TAB_N - 1)) {
            int   i = (int)t;
            float f = t - (float)i;
            float2 ga = g_tab[i];
            float2 gb = g_tab[i + 1];
            g0 = fmaf(f, gb.x - ga.x, ga.x);
            g1 = fmaf(f, gb.y - ga.y, ga.y);
        } else {
            // essentially-never path (d < ~6e-6 or d > ~55); exact math
            eval_exact(feat, W1, b1, pa, pb, W2, b2, g0, g1);
        }

        float c = g1 * sv.w * inv_d;      // out1 * strength / d
        a0 = fmaf(g0, sv.w, a0);          // scalar field
        a1 = fmaf(c, dx, a1);             // vector field
        a2 = fmaf(c, dy, a2);
        a3 = fmaf(c, dz, a3);
    }

    s_red[row][lane] = make_float4(a0, a1, a2, a3);
    __syncthreads();

    if (row == 0) {
        float4 acc = s_red[0][lane];
#pragma unroll
        for (int r = 1; r < 8; ++r) {
            float4 v = s_red[r][lane];
            acc.x += v.x; acc.y += v.y; acc.z += v.z; acc.w += v.w;
        }
        ((float4*)out)[tg] = acc;
    }
}

extern "C" void kernel_launch(void* const* d_in, const int* in_sizes, int n_in,
                              void* d_out, int out_size)
{
    (void)in_sizes; (void)n_in; (void)out_size;
    const float* ref_len = (const float*)d_in[0];
    const float* sp      = (const float*)d_in[1];
    const float* tp      = (const float*)d_in[2];
    const float* q       = (const float*)d_in[3];
    const float* W1      = (const float*)d_in[4];
    const float* b1      = (const float*)d_in[5];
    const float* pa      = (const float*)d_in[6];
    const float* pb      = (const float*)d_in[7];
    const float* W2      = (const float*)d_in[8];
    const float* b2      = (const float*)d_in[9];
    float* out = (float*)d_out;

    build_table_kernel<<<TAB_N / 256, 256>>>(W1, b1, pa, pb, W2, b2);
    field_kernel<<<NT / 32, 256>>>(ref_len, sp, tp, q, W1, b1, pa, pb, W2, b2, out);
}